// round 1
// baseline (speedup 1.0000x reference)
#include <cuda_runtime.h>
#include <math.h>

// Problem constants
#define B        64
#define DV       1024
#define NQ       32
#define NS       1024
#define D        128
#define NEG_MASK 1000000.0f
#define ALPHA    0.5f

// Intermediate score matrices (device globals: no allocation allowed)
__device__ float g_scores[B * B];   // single-vector scores
__device__ float g_mscores[B * B];  // multi-vector scores

// ---------------------------------------------------------------------------
// Kernel 1: single-vector scores[b][c] = dot(q_single[b], d_single[c]) (K=1024)
// grid = 64 (b), block = 256 (8 warps). Each warp handles 8 c's via lane-strided
// coalesced loads of d and a shuffle reduce.
// ---------------------------------------------------------------------------
__global__ void __launch_bounds__(256) k_single(const float* __restrict__ q,
                                                const float* __restrict__ d) {
    __shared__ float qs[DV];
    const int b = blockIdx.x;
    for (int i = threadIdx.x; i < DV; i += 256) qs[i] = q[b * DV + i];
    __syncthreads();

    const int w    = threadIdx.x >> 5;
    const int lane = threadIdx.x & 31;
    for (int cc = 0; cc < 8; cc++) {
        const int c = cc * 8 + w;
        const float* dv = d + c * DV;
        float p = 0.0f;
        #pragma unroll 8
        for (int i = lane; i < DV; i += 32) p += qs[i] * dv[i];
        #pragma unroll
        for (int o = 16; o; o >>= 1) p += __shfl_xor_sync(0xffffffffu, p, o);
        if (lane == 0) g_scores[b * B + c] = p;
    }
}

// ---------------------------------------------------------------------------
// Kernel 2: multi-vector late-interaction scores.
// For row tile rt (64 (b,n)-rows = 2 full b's) and doc c:
//   sim[r][s] = sum_k A[r][k] * Dm[c][s][k],  r in [rt*64, rt*64+64), s in [0,1024)
//   rowmax[r] = max_s sim[r][s];  g_mscores[b][c] = sum over the 32 n-rows of b.
// Smem: A k-major [128][64] (32KB, loaded once) + B k-major [64][64] (16KB,
// reloaded per 64-k half per 64-s tile) = 48KB static. 256 threads, 4x4 micro.
// ---------------------------------------------------------------------------
__global__ void __launch_bounds__(256) k_multi(const float* __restrict__ qm,
                                               const float* __restrict__ dm) {
    __shared__ float As[D * 64];   // As[k*64 + r]
    __shared__ float Bs[64 * 64];  // Bs[k*64 + s], one 64-wide k half at a time

    const int rt  = blockIdx.x;   // 0..31
    const int c   = blockIdx.y;   // 0..63
    const int tid = threadIdx.x;  // 0..255

    const float* Ag = qm + (size_t)rt * 64 * D;       // 64 rows x 128 k
    const float* Dg = dm + (size_t)c * NS * D;        // 1024 rows x 128 k

    // Load A: 64 rows x 32 float4s = 2048 float4s; 8 per thread, coalesced.
    #pragma unroll
    for (int i = 0; i < 8; i++) {
        int idx = tid + i * 256;
        int r  = idx >> 5;   // row 0..63
        int kc = idx & 31;   // float4 index along k
        float4 v = ((const float4*)Ag)[r * 32 + kc];
        As[(kc * 4 + 0) * 64 + r] = v.x;
        As[(kc * 4 + 1) * 64 + r] = v.y;
        As[(kc * 4 + 2) * 64 + r] = v.z;
        As[(kc * 4 + 3) * 64 + r] = v.w;
    }

    const int ty = tid >> 4;   // 0..15 -> rows ty*4..ty*4+3
    const int tx = tid & 15;   // 0..15 -> cols tx*4..tx*4+3

    float mx0 = -3.0e38f, mx1 = -3.0e38f, mx2 = -3.0e38f, mx3 = -3.0e38f;

    for (int st = 0; st < 16; st++) {              // 16 s-tiles of 64
        float acc[4][4];
        #pragma unroll
        for (int i = 0; i < 4; i++)
            #pragma unroll
            for (int j = 0; j < 4; j++) acc[i][j] = 0.0f;

        #pragma unroll
        for (int kc2 = 0; kc2 < 2; kc2++) {        // two 64-wide k halves
            __syncthreads();                       // protect prior Bs readers
            const float* Bg = Dg + (size_t)st * 64 * D + kc2 * 64;
            #pragma unroll
            for (int i = 0; i < 4; i++) {          // 1024 float4s, 4/thread
                int idx = tid + i * 256;
                int s  = idx >> 4;                 // 0..63
                int k4 = idx & 15;                 // float4 along the 64-k half
                float4 v = *(const float4*)(Bg + s * D + k4 * 4);
                Bs[(k4 * 4 + 0) * 64 + s] = v.x;
                Bs[(k4 * 4 + 1) * 64 + s] = v.y;
                Bs[(k4 * 4 + 2) * 64 + s] = v.z;
                Bs[(k4 * 4 + 3) * 64 + s] = v.w;
            }
            __syncthreads();

            const int kb = kc2 * 64;
            #pragma unroll 8
            for (int k = 0; k < 64; k++) {
                float4 a = *(const float4*)&As[(kb + k) * 64 + ty * 4];
                float4 b = *(const float4*)&Bs[k * 64 + tx * 4];
                acc[0][0] += a.x * b.x; acc[0][1] += a.x * b.y;
                acc[0][2] += a.x * b.z; acc[0][3] += a.x * b.w;
                acc[1][0] += a.y * b.x; acc[1][1] += a.y * b.y;
                acc[1][2] += a.y * b.z; acc[1][3] += a.y * b.w;
                acc[2][0] += a.z * b.x; acc[2][1] += a.z * b.y;
                acc[2][2] += a.z * b.z; acc[2][3] += a.z * b.w;
                acc[3][0] += a.w * b.x; acc[3][1] += a.w * b.y;
                acc[3][2] += a.w * b.z; acc[3][3] += a.w * b.w;
            }
        }
        // fold this s-tile into the running per-row maxima
        mx0 = fmaxf(mx0, fmaxf(fmaxf(acc[0][0], acc[0][1]), fmaxf(acc[0][2], acc[0][3])));
        mx1 = fmaxf(mx1, fmaxf(fmaxf(acc[1][0], acc[1][1]), fmaxf(acc[1][2], acc[1][3])));
        mx2 = fmaxf(mx2, fmaxf(fmaxf(acc[2][0], acc[2][1]), fmaxf(acc[2][2], acc[2][3])));
        mx3 = fmaxf(mx3, fmaxf(fmaxf(acc[3][0], acc[3][1]), fmaxf(acc[3][2], acc[3][3])));
    }

    // Cross-tx max reduce per row (reuse As as scratch: [64 rows][16 tx])
    __syncthreads();
    float* red = As;
    red[(ty * 4 + 0) * 16 + tx] = mx0;
    red[(ty * 4 + 1) * 16 + tx] = mx1;
    red[(ty * 4 + 2) * 16 + tx] = mx2;
    red[(ty * 4 + 3) * 16 + tx] = mx3;
    __syncthreads();

    if (tid < 64) {
        float m = red[tid * 16 + 0];
        #pragma unroll
        for (int j = 1; j < 16; j++) m = fmaxf(m, red[tid * 16 + j]);
        Bs[tid] = m;   // rowmax[r]
    }
    __syncthreads();

    if (tid == 0) {
        float s0 = 0.0f;
        #pragma unroll
        for (int n = 0; n < NQ; n++) s0 += Bs[n];
        g_mscores[(2 * rt + 0) * B + c] = s0;
    }
    if (tid == 32) {
        float s1 = 0.0f;
        #pragma unroll
        for (int n = 0; n < NQ; n++) s1 += Bs[32 + n];
        g_mscores[(2 * rt + 1) * B + c] = s1;
    }
}

// ---------------------------------------------------------------------------
// Kernel 3: epilogues. 1 block, 64 threads (one per b).
// sv = sum_b (logsumexp(scores[b,:]) - scores[b,b])
// mv = mean_b softplus(max_c(mscores[b,c] - eye*NEG_MASK) - mscores[b,b])
// out = ALPHA*sv + (1-ALPHA)*mv
// ---------------------------------------------------------------------------
__global__ void k_final(float* __restrict__ out) {
    __shared__ float s_sv[B];
    __shared__ float s_mv[B];
    const int b = threadIdx.x;

    // single-vector CE term
    const float* row = g_scores + b * B;
    float mx = -3.0e38f;
    for (int c = 0; c < B; c++) mx = fmaxf(mx, row[c]);
    float se = 0.0f;
    for (int c = 0; c < B; c++) se += expf(row[c] - mx);
    float lse = mx + logf(se);
    s_sv[b] = lse - row[b];

    // multi-vector margin term
    const float* mrow = g_mscores + b * B;
    float pos = mrow[b];
    float neg = -3.0e38f;
    for (int c = 0; c < B; c++) {
        float v = mrow[c] - (c == b ? NEG_MASK : 0.0f);
        neg = fmaxf(neg, v);
    }
    float x  = neg - pos;
    float sp = fmaxf(x, 0.0f) + log1pf(expf(-fabsf(x)));  // stable softplus
    s_mv[b] = sp;

    __syncthreads();
    if (b == 0) {
        float sv = 0.0f, mv = 0.0f;
        for (int i = 0; i < B; i++) { sv += s_sv[i]; mv += s_mv[i]; }
        mv *= (1.0f / B);
        out[0] = ALPHA * sv + (1.0f - ALPHA) * mv;
    }
}

// ---------------------------------------------------------------------------
extern "C" void kernel_launch(void* const* d_in, const int* in_sizes, int n_in,
                              void* d_out, int out_size) {
    const float* q_single = (const float*)d_in[0];  // [64, 1024]
    const float* d_single = (const float*)d_in[1];  // [64, 1024]
    const float* q_multi  = (const float*)d_in[2];  // [64, 32, 128]
    const float* d_multi  = (const float*)d_in[3];  // [64, 1024, 128]
    float* out = (float*)d_out;

    k_single<<<B, 256>>>(q_single, d_single);
    k_multi<<<dim3(32, B), 256>>>(q_multi, d_multi);
    k_final<<<1, B>>>(out);
}

// round 3
// speedup vs baseline: 11.1194x; 11.1194x over previous
#include <cuda_runtime.h>
#include <cuda_bf16.h>
#include <cstdint>
#include <math.h>

#define B        64
#define DV       1024
#define NQ       32
#define NS       1024
#define D        128
#define NEG_MASK 1000000.0f
#define ALPHA    0.5f
#define LDP      136   // padded smem row stride (bf16 elems): 272B -> conflict-free ldmatrix

// dynamic smem arena offsets (bytes)
#define OFF_AS   0
#define OFF_BS   34816              // 128*136*2
#define OFF_RED  69632              // 2*34816
#define SMEM_TOT 70656              // + 2*128*4

__device__ float g_part[4 * B * B];   // k-split partial single-vector scores
__device__ float g_mscores[B * B];    // multi-vector scores

// ---------------------------------------------------------------------------
// PTX helpers
// ---------------------------------------------------------------------------
__device__ __forceinline__ void ldsm_x4(unsigned int* r, unsigned int addr) {
    asm volatile("ldmatrix.sync.aligned.m8n8.x4.shared.b16 {%0,%1,%2,%3}, [%4];"
                 : "=r"(r[0]), "=r"(r[1]), "=r"(r[2]), "=r"(r[3]) : "r"(addr));
}
__device__ __forceinline__ void ldsm_x2(unsigned int* r, unsigned int addr) {
    asm volatile("ldmatrix.sync.aligned.m8n8.x2.shared.b16 {%0,%1}, [%2];"
                 : "=r"(r[0]), "=r"(r[1]) : "r"(addr));
}
__device__ __forceinline__ void mma_16816(float* c, const unsigned int* a,
                                          const unsigned int* b) {
    asm volatile("mma.sync.aligned.m16n8k16.row.col.f32.bf16.bf16.f32 "
                 "{%0,%1,%2,%3}, {%4,%5,%6,%7}, {%8,%9}, {%0,%1,%2,%3};"
                 : "+f"(c[0]), "+f"(c[1]), "+f"(c[2]), "+f"(c[3])
                 : "r"(a[0]), "r"(a[1]), "r"(a[2]), "r"(a[3]), "r"(b[0]), "r"(b[1]));
}

// ---------------------------------------------------------------------------
// Kernel 1: single-vector partial scores, k-split by 4.
// grid (64 b, 4 kc), block 256. g_part[kc][b][c] = dot over k-chunk of 256.
// ---------------------------------------------------------------------------
__global__ void __launch_bounds__(256) k_single(const float* __restrict__ q,
                                                const float* __restrict__ d) {
    __shared__ float qs[256];
    const int b   = blockIdx.x;
    const int kc  = blockIdx.y;
    const int tid = threadIdx.x;
    qs[tid] = q[b * DV + kc * 256 + tid];
    __syncthreads();

    const int w    = tid >> 5;
    const int lane = tid & 31;
    #pragma unroll
    for (int cc = 0; cc < 8; cc++) {
        const int c = cc * 8 + w;
        const float* dv = d + c * DV + kc * 256;
        float p = 0.0f;
        #pragma unroll
        for (int i = lane; i < 256; i += 32) {
            p += qs[i] * dv[i];
        }
        #pragma unroll
        for (int o = 16; o; o >>= 1) {
            p += __shfl_xor_sync(0xffffffffu, p, o);
        }
        if (lane == 0) g_part[(kc * B + b) * B + c] = p;
    }
}

// ---------------------------------------------------------------------------
// Kernel 2: multi-vector late interaction, bf16 mma.sync tensor cores.
// grid (16 rt, 64 c). Block: 128 (b,n)-rows (4 b's) x all 1024 s of doc c.
// 8 warps as 4(m32) x 2(n64) over each 128-wide s-tile.
// ---------------------------------------------------------------------------
__global__ void __launch_bounds__(256, 2) k_multi_tc(const float* __restrict__ qm,
                                                     const float* __restrict__ dm) {
    extern __shared__ char smem_raw[];
    __nv_bfloat16* As = (__nv_bfloat16*)(smem_raw + OFF_AS);   // [row][k]
    __nv_bfloat16* Bs = (__nv_bfloat16*)(smem_raw + OFF_BS);   // [s][k]
    float* redbuf     = (float*)(smem_raw + OFF_RED);          // [2][128]

    const int rt   = blockIdx.x;   // 0..15 -> rows rt*128..
    const int c    = blockIdx.y;   // 0..63
    const int tid  = threadIdx.x;
    const int lane = tid & 31;
    const int warp = tid >> 5;
    const int wm   = warp >> 1;    // 0..3
    const int wn   = warp & 1;     // 0..1

    // Load A: 128 rows x 128 k fp32 -> bf16 (4096 float4s, 16/thread)
    const float4* Ag = (const float4*)(qm + (size_t)rt * 128 * D);
    #pragma unroll
    for (int i = 0; i < 16; i++) {
        int idx = tid + i * 256;
        int r   = idx >> 5;
        int k4  = idx & 31;
        float4 v = Ag[idx];
        __nv_bfloat16* p = &As[r * LDP + k4 * 4];
        *(__nv_bfloat162*)(p)     = __floats2bfloat162_rn(v.x, v.y);
        *(__nv_bfloat162*)(p + 2) = __floats2bfloat162_rn(v.z, v.w);
    }

    // ldmatrix lane addresses (hoisted)
    const int arow = lane & 15;
    const int acol = (lane >> 4) * 8;
    unsigned int a_addr0 = (unsigned int)__cvta_generic_to_shared(
        &As[(wm * 32 + arow) * LDP + acol]);
    unsigned int a_addr1 = a_addr0 + 16 * LDP * 2;   // +16 rows

    const int brow = lane & 7;
    const int bcol = ((lane >> 3) & 1) * 8;
    unsigned int b_addr = (unsigned int)__cvta_generic_to_shared(
        &Bs[(wn * 64 + brow) * LDP + bcol]);

    float rmax00 = -3.0e38f, rmax01 = -3.0e38f;
    float rmax10 = -3.0e38f, rmax11 = -3.0e38f;

    const float4* Dg = (const float4*)(dm + (size_t)c * NS * D);

    for (int st = 0; st < 8; st++) {             // 8 s-tiles of 128
        __syncthreads();                          // protect Bs from prior readers
        const float4* Bg = Dg + st * (128 * 32);
        #pragma unroll
        for (int i = 0; i < 16; i++) {
            int idx = tid + i * 256;
            int s   = idx >> 5;
            int k4  = idx & 31;
            float4 v = Bg[idx];
            __nv_bfloat16* p = &Bs[s * LDP + k4 * 4];
            *(__nv_bfloat162*)(p)     = __floats2bfloat162_rn(v.x, v.y);
            *(__nv_bfloat162*)(p + 2) = __floats2bfloat162_rn(v.z, v.w);
        }
        __syncthreads();

        float acc[2][8][4];
        #pragma unroll
        for (int mt = 0; mt < 2; mt++) {
            #pragma unroll
            for (int nt = 0; nt < 8; nt++) {
                acc[mt][nt][0] = 0.0f; acc[mt][nt][1] = 0.0f;
                acc[mt][nt][2] = 0.0f; acc[mt][nt][3] = 0.0f;
            }
        }

        #pragma unroll
        for (int kt = 0; kt < 8; kt++) {
            unsigned int a0[4], a1[4];
            ldsm_x4(a0, a_addr0 + kt * 32);
            ldsm_x4(a1, a_addr1 + kt * 32);
            #pragma unroll
            for (int nt = 0; nt < 8; nt++) {
                unsigned int bfr[2];
                ldsm_x2(bfr, b_addr + nt * (8 * LDP * 2) + kt * 32);
                mma_16816(acc[0][nt], a0, bfr);
                mma_16816(acc[1][nt], a1, bfr);
            }
        }

        // fold s-tile into running per-row maxima
        #pragma unroll
        for (int mt = 0; mt < 2; mt++) {
            float m0 = -3.0e38f, m1 = -3.0e38f;
            #pragma unroll
            for (int nt = 0; nt < 8; nt++) {
                m0 = fmaxf(m0, fmaxf(acc[mt][nt][0], acc[mt][nt][1]));
                m1 = fmaxf(m1, fmaxf(acc[mt][nt][2], acc[mt][nt][3]));
            }
            if (mt == 0) { rmax00 = fmaxf(rmax00, m0); rmax01 = fmaxf(rmax01, m1); }
            else         { rmax10 = fmaxf(rmax10, m0); rmax11 = fmaxf(rmax11, m1); }
        }
    }

    // cross-lane max: lanes l^1, l^2 hold other columns of the same row
    {
        float v;
        v = rmax00; v = fmaxf(v, __shfl_xor_sync(0xffffffffu, v, 1));
        v = fmaxf(v, __shfl_xor_sync(0xffffffffu, v, 2)); rmax00 = v;
        v = rmax01; v = fmaxf(v, __shfl_xor_sync(0xffffffffu, v, 1));
        v = fmaxf(v, __shfl_xor_sync(0xffffffffu, v, 2)); rmax01 = v;
        v = rmax10; v = fmaxf(v, __shfl_xor_sync(0xffffffffu, v, 1));
        v = fmaxf(v, __shfl_xor_sync(0xffffffffu, v, 2)); rmax10 = v;
        v = rmax11; v = fmaxf(v, __shfl_xor_sync(0xffffffffu, v, 1));
        v = fmaxf(v, __shfl_xor_sync(0xffffffffu, v, 2)); rmax11 = v;
    }
    if ((lane & 3) == 0) {
        const int rg = lane >> 2;                 // 0..7
        float* rb = redbuf + wn * 128 + wm * 32;
        rb[rg]          = rmax00;
        rb[rg + 8]      = rmax01;
        rb[16 + rg]     = rmax10;
        rb[16 + rg + 8] = rmax11;
    }
    __syncthreads();

    // row tid (0..127): combine wn halves; each warp sums its 32 rows (= one b)
    if (tid < 128) {
        float m = fmaxf(redbuf[tid], redbuf[128 + tid]);
        #pragma unroll
        for (int o = 16; o; o >>= 1) {
            m += __shfl_xor_sync(0xffffffffu, m, o);
        }
        if (lane == 0) g_mscores[(rt * 4 + warp) * B + c] = m;
    }
}

// ---------------------------------------------------------------------------
// Kernel 3: epilogues (1 block, 64 threads)
// ---------------------------------------------------------------------------
__global__ void k_final(float* __restrict__ out) {
    __shared__ float s_sv[B];
    __shared__ float s_mv[B];
    const int b = threadIdx.x;

    float row[B];
    #pragma unroll 8
    for (int c = 0; c < B; c++) {
        float s = 0.0f;
        s += g_part[(0 * B + b) * B + c];
        s += g_part[(1 * B + b) * B + c];
        s += g_part[(2 * B + b) * B + c];
        s += g_part[(3 * B + b) * B + c];
        row[c] = s;
    }
    float mx = -3.0e38f;
    for (int c = 0; c < B; c++) mx = fmaxf(mx, row[c]);
    float se = 0.0f;
    for (int c = 0; c < B; c++) se += expf(row[c] - mx);
    s_sv[b] = mx + logf(se) - row[b];

    const float* mrow = g_mscores + b * B;
    float pos = mrow[b];
    float neg = -3.0e38f;
    for (int c = 0; c < B; c++) {
        float v = mrow[c] - (c == b ? NEG_MASK : 0.0f);
        neg = fmaxf(neg, v);
    }
    float x = neg - pos;
    s_mv[b] = fmaxf(x, 0.0f) + log1pf(expf(-fabsf(x)));

    __syncthreads();
    if (b == 0) {
        float sv = 0.0f, mv = 0.0f;
        for (int i = 0; i < B; i++) { sv += s_sv[i]; mv += s_mv[i]; }
        out[0] = ALPHA * sv + (1.0f - ALPHA) * (mv / B);
    }
}

// ---------------------------------------------------------------------------
extern "C" void kernel_launch(void* const* d_in, const int* in_sizes, int n_in,
                              void* d_out, int out_size) {
    const float* q_single = (const float*)d_in[0];  // [64, 1024]
    const float* d_single = (const float*)d_in[1];  // [64, 1024]
    const float* q_multi  = (const float*)d_in[2];  // [64, 32, 128]
    const float* d_multi  = (const float*)d_in[3];  // [64, 1024, 128]
    float* out = (float*)d_out;

    cudaFuncSetAttribute(k_multi_tc, cudaFuncAttributeMaxDynamicSharedMemorySize,
                         SMEM_TOT);

    k_single<<<dim3(B, 4), 256>>>(q_single, d_single);
    k_multi_tc<<<dim3(16, B), 256, SMEM_TOT>>>(q_multi, d_multi);
    k_final<<<1, B>>>(out);
}